// round 11
// baseline (speedup 1.0000x reference)
#include <cuda_runtime.h>

#define HID   64
#define BATCH 16
#define SEQ   512
#define VOCAB 32000
#define NTOK  (BATCH * SEQ * 2)     // 16384
#define RPB   8                     // rows per rowvec block (1 per warp)
#define NRVB  (NTOK / RPB)          // 2048

// Scratch (no device allocs allowed). __device__ globals start zeroed, so
// stale g_rowlist/g_slot entries are always valid indices; only g_cnt_v and
// g_nrows must be cleared each launch.
__device__ int   g_cnt_v[VOCAB];          // dedup flag (zeroed each launch)
__device__ int   g_slot[VOCAB];           // v -> worklist slot
__device__ int   g_rowlist[NTOK];         // distinct rows
__device__ int   g_nrows[1];
__device__ float g_rowvec[NTOK * HID];    // r_v = sos . E_v  (4 MB)

// ---------------------------------------------------------------- zero
__global__ __launch_bounds__(256) void zero_kernel() {
    const int i = blockIdx.x * 256 + threadIdx.x;
    if (i < VOCAB / 4)
        reinterpret_cast<int4*>(g_cnt_v)[i] = make_int4(0, 0, 0, 0);
    if (i == 0) g_nrows[0] = 0;
}

// ---------------------------------------------------------------- histogram
// First toucher of row v claims a worklist slot and records v -> slot.
__global__ __launch_bounds__(256) void hist_kernel(
    const int* __restrict__ s1, const int* __restrict__ s2)
{
    const int t = blockIdx.x * 256 + threadIdx.x;    // 0..16383
    const int b = t >> 10;
    const int l = t & 1023;
    const int v = (l < SEQ) ? s1[b * SEQ + l] : s2[b * SEQ + (l - SEQ)];
    if (atomicAdd(&g_cnt_v[v], 1) == 0) {
        const int pos = atomicAdd(&g_nrows[0], 1);
        g_rowlist[pos] = v;
        g_slot[v] = pos;
    }
}

// ---------------------------------------------------------------- rowvec
// WARP-PER-ROW, fully unrolled: lane loads float4 f = lane + 32j (each
// warp-load = 512B contiguous), ONE register float4 accumulator.
// hg = lane&15 is j-invariant; w = (lane>>4) + 2j. No shared partials,
// no syncs in the hot path. shfl_xor(16) merges half-warps; 16 lanes
// store 256B coalesced.
__global__ __launch_bounds__(256) void rowvec_kernel(
    const float* __restrict__ embed,
    const float* __restrict__ sos)
{
    __shared__ float s_sos[HID];
    __shared__ int   s_row[RPB];

    const int tid  = threadIdx.x;
    const int base = blockIdx.x * RPB;

    if (base >= g_nrows[0]) return;          // block-level early exit

    if (tid < HID) s_sos[tid] = sos[tid];
    if (tid < RPB) s_row[tid] = g_rowlist[base + tid];  // stale-safe
    __syncthreads();

    const int wid  = tid >> 5;               // warp = row
    const int lane = tid & 31;
    const int wb   = lane >> 4;              // 0 or 1 (w parity)

    const float4* row = reinterpret_cast<const float4*>(embed)
                        + ((long long)s_row[wid] << 10);

    float4 acc = make_float4(0.f, 0.f, 0.f, 0.f);
    #pragma unroll
    for (int j = 0; j < 32; j++) {
        const float4 v = __ldg(&row[lane + (j << 5)]);
        const float  s = s_sos[wb + (j << 1)];
        acc.x = fmaf(s, v.x, acc.x); acc.y = fmaf(s, v.y, acc.y);
        acc.z = fmaf(s, v.z, acc.z); acc.w = fmaf(s, v.w, acc.w);
    }

    acc.x += __shfl_xor_sync(0xffffffffu, acc.x, 16);
    acc.y += __shfl_xor_sync(0xffffffffu, acc.y, 16);
    acc.z += __shfl_xor_sync(0xffffffffu, acc.z, 16);
    acc.w += __shfl_xor_sync(0xffffffffu, acc.w, 16);

    if (lane < 16)
        reinterpret_cast<float4*>(&g_rowvec[(base + wid) * HID])[lane] = acc;
}

// ---------------------------------------------------------------- fused accum+MLP
// One block per batch, 512 threads. Atomic-free, deterministic.
// Phase A: stage all 1024 token->slot mappings AND w1 (transposed, pad-65).
// Phase B: thread (lane = tid>>4 in 0..31, hg = tid&15) sums 32 tokens'
// float4s from L2-resident g_rowvec -> 32 independent loads per thread.
// Reduce 32 lane-partials per hg, then layer1+ReLU+layer2 in-block.
#define W1T_STRIDE 65
__global__ __launch_bounds__(512) void accum_mlp_kernel(
    const int*   __restrict__ s1,
    const int*   __restrict__ s2,
    const float* __restrict__ w1,
    const float* __restrict__ b1,
    const float* __restrict__ w2,
    const float* __restrict__ b2,
    float*       __restrict__ out)
{
    __shared__ int    s_slot[1024];
    __shared__ float  w1t[HID * W1T_STRIDE];   // 16.6 KB
    __shared__ float4 s_red[512];              // 8 KB
    __shared__ float  sh[HID];
    __shared__ float  sx[HID];

    const int b   = blockIdx.x;
    const int tid = threadIdx.x;

    // Phase A: token -> slot (2 per thread) + w1 staging (8 per thread).
    #pragma unroll
    for (int j = 0; j < 2; j++) {
        const int l = tid + (j << 9);             // 0..1023
        const int v = (l < SEQ) ? s1[b * SEQ + l]
                                : s2[b * SEQ + (l - SEQ)];
        s_slot[l] = g_slot[v];
    }
    #pragma unroll
    for (int j = 0; j < 8; j++) {
        const int idx = tid + (j << 9);           // 0..4095
        w1t[(idx & 63) * W1T_STRIDE + (idx >> 6)] = w1[idx];
    }
    __syncthreads();

    // Phase B: 32 independent scattered float4 loads per thread.
    const int lane = tid >> 4;    // 0..31 token sub-group
    const int hg   = tid & 15;
    const float4* rv = reinterpret_cast<const float4*>(g_rowvec);

    float4 acc = make_float4(0.f, 0.f, 0.f, 0.f);
    #pragma unroll 8
    for (int i = 0; i < 32; i++) {
        const int idx = s_slot[(lane << 5) + i];
        const float4 p = __ldg(&rv[idx * 16 + hg]);
        acc.x += p.x; acc.y += p.y; acc.z += p.z; acc.w += p.w;
    }
    s_red[tid] = acc;
    __syncthreads();

    // Reduce 32 lane-partials per h-group (fixed order -> deterministic).
    if (tid < 16) {
        float4 sum = make_float4(0.f, 0.f, 0.f, 0.f);
        #pragma unroll
        for (int j = 0; j < 32; j++) {
            const float4 p = s_red[(j << 4) + tid];
            sum.x += p.x; sum.y += p.y; sum.z += p.z; sum.w += p.w;
        }
        reinterpret_cast<float4*>(sh)[tid] = sum;
    }
    __syncthreads();

    // Layer 1 + ReLU (threads 0..63; sh broadcast; w1t conflict-free).
    if (tid < HID) {
        float sum = b1[tid];
        #pragma unroll
        for (int k = 0; k < HID; k++)
            sum = fmaf(sh[k], w1t[k * W1T_STRIDE + tid], sum);
        sx[tid] = fmaxf(sum, 0.0f);
    }
    __syncthreads();

    // Layer 2: 2 outputs for this batch.
    if (tid < 2) {
        float s2v = b2[tid];
        #pragma unroll
        for (int k = 0; k < HID; k++)
            s2v = fmaf(sx[k], w2[tid * HID + k], s2v);
        out[b * 2 + tid] = s2v;
    }
}

extern "C" void kernel_launch(void* const* d_in, const int* in_sizes, int n_in,
                              void* d_out, int out_size)
{
    const int*   s1    = (const int*)  d_in[0];
    const int*   s2    = (const int*)  d_in[1];
    const float* embed = (const float*)d_in[2];
    const float* sos   = (const float*)d_in[3];
    const float* w1    = (const float*)d_in[4];
    const float* b1    = (const float*)d_in[5];
    const float* w2    = (const float*)d_in[6];
    const float* b2    = (const float*)d_in[7];
    float* out = (float*)d_out;

    zero_kernel<<<(VOCAB / 4 + 255) / 256, 256>>>();
    hist_kernel<<<NTOK / 256, 256>>>(s1, s2);
    rowvec_kernel<<<NRVB, 256>>>(embed, sos);
    accum_mlp_kernel<<<BATCH, 512>>>(s1, s2, w1, b1, w2, b2, out);
}